// round 14
// baseline (speedup 1.0000x reference)
#include <cuda_runtime.h>
#include <cuda_fp16.h>
#include <math.h>
#include <stdint.h>

#define B_  2
#define T_  2048
#define D_  2048
#define H_  16
#define DH  128
#define MROWS (B_*T_)          // 4096
#define QKV_N (3*D_)           // 6144

// Scratch (device globals — no allocation allowed); all fp16 operands
__device__ __half g_qkv[(size_t)MROWS * QKV_N];    // 50 MB (Q pre-scaled)
__device__ __half g_o[(size_t)MROWS * D_];         // 16 MB
__device__ __half g_xh[(size_t)MROWS * D_];        // 16 MB
__device__ __half g_WqkvT[(size_t)QKV_N * D_];     // 25 MB ([N,K] K-contig)
__device__ __half g_WoutT[(size_t)D_ * D_];        // 8 MB

#define ATT_SCALE 0.08838834764831845f   // 1/sqrt(128)

// ---------------------------------------------------------------------------
// Helpers
// ---------------------------------------------------------------------------
__device__ __forceinline__ void cp_async16(uint32_t s, const void* g) {
    asm volatile("cp.async.cg.shared.global [%0], [%1], 16;" :: "r"(s), "l"(g));
}
__device__ __forceinline__ void cp_commit() {
    asm volatile("cp.async.commit_group;" ::: "memory");
}
template <int N> __device__ __forceinline__ void cp_wait() {
    asm volatile("cp.async.wait_group %0;" :: "n"(N) : "memory");
}
__device__ __forceinline__ uint32_t smem_u32(const void* p) {
    uint32_t a;
    asm("{ .reg .u64 t; cvta.to.shared.u64 t, %1; cvt.u32.u64 %0, t; }"
        : "=r"(a) : "l"(p));
    return a;
}
__device__ __forceinline__ void ldm_x4(uint32_t& r0, uint32_t& r1,
                                       uint32_t& r2, uint32_t& r3, uint32_t a) {
    asm volatile("ldmatrix.sync.aligned.m8n8.x4.shared.b16 {%0,%1,%2,%3}, [%4];"
                 : "=r"(r0), "=r"(r1), "=r"(r2), "=r"(r3) : "r"(a));
}
__device__ __forceinline__ void ldm_x4_t(uint32_t& r0, uint32_t& r1,
                                         uint32_t& r2, uint32_t& r3, uint32_t a) {
    asm volatile("ldmatrix.sync.aligned.m8n8.x4.trans.shared.b16 {%0,%1,%2,%3}, [%4];"
                 : "=r"(r0), "=r"(r1), "=r"(r2), "=r"(r3) : "r"(a));
}
__device__ __forceinline__ void mma_f16(float c[4],
    uint32_t a0, uint32_t a1, uint32_t a2, uint32_t a3,
    uint32_t b0, uint32_t b1)
{
    asm volatile(
        "mma.sync.aligned.m16n8k16.row.col.f32.f16.f16.f32 "
        "{%0,%1,%2,%3}, {%4,%5,%6,%7}, {%8,%9}, {%0,%1,%2,%3};"
        : "+f"(c[0]), "+f"(c[1]), "+f"(c[2]), "+f"(c[3])
        : "r"(a0), "r"(a1), "r"(a2), "r"(a3), "r"(b0), "r"(b1));
}
__device__ __forceinline__ uint32_t pack_h2(float x, float y) {
    __half2 h = __floats2half2_rn(x, y);
    return *(uint32_t*)&h;
}

// ---------------------------------------------------------------------------
// x pre-pass: fp32 -> fp16. Each thread converts 8 floats.
// ---------------------------------------------------------------------------
__global__ __launch_bounds__(256) void f2h_kernel(
    const float* __restrict__ in, __half* __restrict__ out)
{
    const size_t i = (size_t)blockIdx.x * 256 + threadIdx.x;
    float4 a = ((const float4*)in)[2 * i];
    float4 b = ((const float4*)in)[2 * i + 1];
    uint4 u;
    u.x = pack_h2(a.x, a.y); u.y = pack_h2(a.z, a.w);
    u.z = pack_h2(b.x, b.y); u.w = pack_h2(b.z, b.w);
    ((uint4*)out)[i] = u;
}

// ---------------------------------------------------------------------------
// Weight transpose + fp16: At[C, R] = h(A[R, C]^T), k(=R) contiguous in At.
// 64x64 tiles; float4 gmem reads, fp16 smem staging, uint4 coalesced stores.
// ---------------------------------------------------------------------------
__global__ __launch_bounds__(256) void transpose_kernel(
    const float* __restrict__ A, __half* __restrict__ At, int R, int C)
{
    __shared__ __half tile[64][72];     // 144B rows (16B-aligned), pad vs conflicts
    const int k0 = blockIdx.y * 64;
    const int n0 = blockIdx.x * 64;
    const int tid = threadIdx.x;

    #pragma unroll
    for (int i = 0; i < 4; i++) {
        int idx = tid + i * 256;        // 0..1023 float4 groups
        int r = idx >> 4;               // k-row 0..63
        int c4 = (idx & 15) * 4;        // n-col
        float4 v = *(const float4*)&A[(size_t)(k0 + r) * C + n0 + c4];
        tile[c4 + 0][r] = __float2half_rn(v.x);
        tile[c4 + 1][r] = __float2half_rn(v.y);
        tile[c4 + 2][r] = __float2half_rn(v.z);
        tile[c4 + 3][r] = __float2half_rn(v.w);
    }
    __syncthreads();

    #pragma unroll
    for (int i = 0; i < 2; i++) {
        int idx = tid + i * 256;        // 0..511 uint4 groups
        int n = idx >> 3;               // 0..63
        int k8 = (idx & 7) * 8;         // 0..56
        *(uint4*)&At[(size_t)(n0 + n) * R + k0 + k8] = *(uint4*)&tile[n][k8];
    }
}

// ---------------------------------------------------------------------------
// fp16 mma.sync GEMM + bias (R12 core, unchanged numerically except optional
// Q-scaling in the epilogue): CTA 128x256, 8 warps, warp tile 64x64,
// 4-stage depth-3 cp.async pipeline, fragment double-buffering, rotated
// stage boundary. 1 CTA/SM (254 regs).
// SCALE_Q: multiply output by ATT_SCALE for cols < D_ (the Q block) so the
// flash softmax works in the pre-scaled domain (exp args become subtracts).
// ---------------------------------------------------------------------------
#define GBM 128
#define GBN 256
#define GBK 64
#define STRH 72
#define A_TILE_H (128 * STRH)                 // 9216 halves
#define B_TILE_H (256 * STRH)                 // 18432 halves
#define STAGE_B  ((A_TILE_H + B_TILE_H) * 2)  // 55296 bytes
#define GSTAGES  4
#define GEMM_SMEM (GSTAGES * STAGE_B)         // 221184

__device__ __forceinline__ void gemm_load_stage(
    const __half* __restrict__ A, const __half* __restrict__ BT, int K,
    uint32_t sa, uint32_t sb, int brow, int bcol, int k0, int tid)
{
    #pragma unroll
    for (int i = 0; i < 4; i++) {           // A: 128 rows x 8 chunks
        int idx = tid + i * 256;            // 0..1023
        int row = idx >> 3;
        int c = idx & 7;
        cp_async16(sa + (row * STRH + c * 8) * 2,
                   &A[(size_t)(brow + row) * K + k0 + c * 8]);
    }
    #pragma unroll
    for (int i = 0; i < 8; i++) {           // B^T: 256 n-rows x 8 chunks
        int idx = tid + i * 256;            // 0..2047
        int row = idx >> 3;
        int c = idx & 7;
        cp_async16(sb + (row * STRH + c * 8) * 2,
                   &BT[(size_t)(bcol + row) * K + k0 + c * 8]);
    }
}

// load one k16 fragment set (8 ldmatrix.x4: 4 A blocks + 4 B blocks)
#define LOAD_FRAGS(FA, FB, sa, sb, ko)                                        \
    do {                                                                      \
        ldm_x4((FA)[0],  (FA)[1],  (FA)[2],  (FA)[3],                         \
               (sa) + (la_off + (ko)) * 2);                                   \
        ldm_x4((FA)[4],  (FA)[5],  (FA)[6],  (FA)[7],                         \
               (sa) + (la_off + 16 * STRH + (ko)) * 2);                       \
        ldm_x4((FA)[8],  (FA)[9],  (FA)[10], (FA)[11],                        \
               (sa) + (la_off + 32 * STRH + (ko)) * 2);                       \
        ldm_x4((FA)[12], (FA)[13], (FA)[14], (FA)[15],                        \
               (sa) + (la_off + 48 * STRH + (ko)) * 2);                       \
        ldm_x4((FB)[0],  (FB)[1],  (FB)[2],  (FB)[3],                         \
               (sb) + (lb_off + (ko)) * 2);                                   \
        ldm_x4((FB)[4],  (FB)[5],  (FB)[6],  (FB)[7],                         \
               (sb) + (lb_off + 16 * STRH + (ko)) * 2);                       \
        ldm_x4((FB)[8],  (FB)[9],  (FB)[10], (FB)[11],                        \
               (sb) + (lb_off + 32 * STRH + (ko)) * 2);                       \
        ldm_x4((FB)[12], (FB)[13], (FB)[14], (FB)[15],                        \
               (sb) + (lb_off + 48 * STRH + (ko)) * 2);                       \
    } while (0)

#define MMA_BLOCK(cur)                                                        \
    do {                                                                      \
        _Pragma("unroll")                                                     \
        for (int j = 0; j < 4; j++) {                                         \
            _Pragma("unroll")                                                 \
            for (int i = 0; i < 4; i++) {                                     \
                mma_f16(acc[i][2 * j],                                        \
                        fa[cur][4 * i], fa[cur][4 * i + 1],                   \
                        fa[cur][4 * i + 2], fa[cur][4 * i + 3],               \
                        fb[cur][4 * j], fb[cur][4 * j + 1]);                  \
                mma_f16(acc[i][2 * j + 1],                                    \
                        fa[cur][4 * i], fa[cur][4 * i + 1],                   \
                        fa[cur][4 * i + 2], fa[cur][4 * i + 3],               \
                        fb[cur][4 * j + 2], fb[cur][4 * j + 3]);              \
            }                                                                 \
        }                                                                     \
    } while (0)

template <bool OUT_HALF, bool SCALE_Q>
__global__ __launch_bounds__(256, 1) void mma_gemm_bias(
    const __half* __restrict__ A, const __half* __restrict__ BT,
    const float* __restrict__ bias, void* __restrict__ Cv,
    int M, int N, int K)
{
    extern __shared__ char sm[];
    const int tid  = threadIdx.x;
    const int wid  = tid >> 5;
    const int lane = tid & 31;
    const int brow = blockIdx.y * GBM;
    const int bcol = blockIdx.x * GBN;
    const int warp_m = wid & 1;            // rows warp_m*64
    const int warp_n = wid >> 1;           // cols warp_n*64
    const int qr = lane >> 2;
    const int qc = lane & 3;

    const uint32_t base = smem_u32(sm);

    float acc[4][8][4];
    #pragma unroll
    for (int mt = 0; mt < 4; mt++)
        #pragma unroll
        for (int nt = 0; nt < 8; nt++)
            #pragma unroll
            for (int i = 0; i < 4; i++)
                acc[mt][nt][i] = 0.0f;

    const int KT = K / GBK;   // 32

    #pragma unroll
    for (int s = 0; s < 3; s++) {
        const uint32_t sa = base + s * STAGE_B;
        gemm_load_stage(A, BT, K, sa, sa + A_TILE_H * 2, brow, bcol,
                        s * GBK, tid);
        cp_commit();
    }

    const int la_off = (warp_m * 64 + (lane & 15)) * STRH + (lane >> 4) * 8;
    const int g = lane >> 3;
    const int lb_off = (warp_n * 64 + ((g & 2) ? 8 : 0) + (lane & 7)) * STRH
                     + (g & 1) * 8;

    uint32_t fa[2][16], fb[2][16];

    cp_wait<2>();
    __syncthreads();
    LOAD_FRAGS(fa[0], fb[0], base, base + A_TILE_H * 2, 0);

    int st = 0;
    for (int kt = 0; kt < KT; kt++) {
        const int lkt = kt + 3;
        if (lkt < KT) {
            int fst = st + 3; if (fst >= GSTAGES) fst -= GSTAGES;
            const uint32_t pa = base + fst * STAGE_B;
            gemm_load_stage(A, BT, K, pa, pa + A_TILE_H * 2, brow, bcol,
                            lkt * GBK, tid);
        }
        cp_commit();

        const uint32_t sa = base + st * STAGE_B;
        const uint32_t sb = sa + A_TILE_H * 2;

        #pragma unroll
        for (int k16 = 0; k16 < 3; k16++) {
            const int cur = k16 & 1, nxt = cur ^ 1;
            LOAD_FRAGS(fa[nxt], fb[nxt], sa, sb, (k16 + 1) * 16);
            MMA_BLOCK(cur);
        }

        cp_wait<2>();
        __syncthreads();
        int nst = st + 1; if (nst >= GSTAGES) nst -= GSTAGES;
        if (kt + 1 < KT) {
            const uint32_t na = base + nst * STAGE_B;
            LOAD_FRAGS(fa[0], fb[0], na, na + A_TILE_H * 2, 0);
        }
        MMA_BLOCK(1);
        st = nst;
    }

    #pragma unroll
    for (int mt = 0; mt < 4; mt++) {
        const int row0 = brow + warp_m * 64 + mt * 16 + qr;
        #pragma unroll
        for (int nt = 0; nt < 8; nt++) {
            const int col = bcol + warp_n * 64 + nt * 8 + 2 * qc;
            const float2 bb = *(const float2*)&bias[col];
            float vx = acc[mt][nt][0] + bb.x;
            float vy = acc[mt][nt][1] + bb.y;
            float wx = acc[mt][nt][2] + bb.x;
            float wy = acc[mt][nt][3] + bb.y;
            if (SCALE_Q && col < D_) {   // Q block: pre-scale for softmax
                vx *= ATT_SCALE; vy *= ATT_SCALE;
                wx *= ATT_SCALE; wy *= ATT_SCALE;
            }
            if (OUT_HALF) {
                __half* C = (__half*)Cv;
                *(uint32_t*)&C[(size_t)row0 * N + col]       = pack_h2(vx, vy);
                *(uint32_t*)&C[(size_t)(row0 + 8) * N + col] = pack_h2(wx, wy);
            } else {
                float* C = (float*)Cv;
                float2 o0; o0.x = vx; o0.y = vy;
                float2 o1; o1.x = wx; o1.y = wy;
                *(float2*)&C[(size_t)row0 * N + col]       = o0;
                *(float2*)&C[(size_t)(row0 + 8) * N + col] = o1;
            }
        }
    }
}

// ---------------------------------------------------------------------------
// fp16 tensor-core flash attention (causal, register softmax, ldmatrix).
// Q arrives pre-scaled by 1/sqrt(Dh) -> exp args are plain subtracts.
// Warp-voted oacc rescale skip when no row-max moved.
// CTA: 128 q-rows, 256 threads. KV tiles of 64, double-buffered cp.async.
// 2 CTAs/SM. Row stride 136 halves. S/PV fragments software-pipelined.
// ---------------------------------------------------------------------------
#define FBQ   128
#define FSTR  136
#define Q_BYTES     (128 * FSTR * 2)          // 34816
#define KV_TILE_B   (64 * FSTR * 2)           // 17408
#define KV_STAGE_B  (2 * KV_TILE_B)           // 34816
#define FLASH_SMEM  (Q_BYTES + 2 * KV_STAGE_B)  // 104448

__device__ __forceinline__ void load_kv_tile(
    uint32_t kbase, uint32_t vbase, size_t rowbase, int j0, int qcol, int tid)
{
    #pragma unroll
    for (int i = 0; i < 4; i++) {
        int idx = tid + i * 256;          // 0..1023
        int r = idx >> 4;                 // 0..63
        int c = idx & 15;
        cp_async16(kbase + (r * FSTR + c * 8) * 2,
                   &g_qkv[(rowbase + j0 + r) * (size_t)QKV_N + qcol + D_ + c * 8]);
    }
    #pragma unroll
    for (int i = 0; i < 4; i++) {
        int idx = tid + i * 256;
        int r = idx >> 4;
        int c = idx & 15;
        cp_async16(vbase + (r * FSTR + c * 8) * 2,
                   &g_qkv[(rowbase + j0 + r) * (size_t)QKV_N + qcol + 2 * D_ + c * 8]);
    }
}

__global__ __launch_bounds__(256, 2) void flash_mma_kernel()
{
    extern __shared__ char smc[];
    const int qi  = (gridDim.x - 1) - blockIdx.x;   // big q-blocks first
    const int q0  = qi * FBQ;
    const int h   = blockIdx.y;
    const int b   = blockIdx.z;
    const int tid = threadIdx.x;
    const int lane = tid & 31;
    const int wid  = tid >> 5;
    const int qr = lane >> 2;
    const int qc = lane & 3;

    const size_t rowbase = (size_t)b * T_;
    const int qcol = h * DH;

    const uint32_t base = smem_u32(smc);
    const uint32_t Qs = base;
    const int ntile = 2 * qi + 2;

    #pragma unroll
    for (int i = 0; i < 8; i++) {
        int idx = tid + i * 256;          // 0..2047
        int r = idx >> 4;
        int c = idx & 15;
        cp_async16(Qs + (r * FSTR + c * 8) * 2,
                   &g_qkv[(rowbase + q0 + r) * (size_t)QKV_N + qcol + c * 8]);
    }
    {
        uint32_t s0 = base + Q_BYTES;
        load_kv_tile(s0, s0 + KV_TILE_B, rowbase, 0, qcol, tid);
        cp_commit();
        if (ntile > 1) {
            uint32_t s1 = base + Q_BYTES + KV_STAGE_B;
            load_kv_tile(s1, s1 + KV_TILE_B, rowbase, 64, qcol, tid);
        }
        cp_commit();
    }

    float oacc[16][4];
    #pragma unroll
    for (int n = 0; n < 16; n++)
        #pragma unroll
        for (int i = 0; i < 4; i++) oacc[n][i] = 0.0f;
    float mrow0 = -3.0e38f, mrow1 = -3.0e38f;
    float lrow0 = 0.0f, lrow1 = 0.0f;

    const int mloc = wid * 16;
    const int g = lane >> 3;
    const int lq_off = (mloc + (lane & 15)) * FSTR + (lane >> 4) * 8;
    const int lk_off = (((g & 2) ? 8 : 0) + (lane & 7)) * FSTR + (g & 1) * 8;
    const int lv_off = ((g & 1) * 8 + (lane & 7)) * FSTR + ((g & 2) ? 8 : 0);

    for (int t = 0; t < ntile; t++) {
        cp_wait<1>();
        __syncthreads();

        const uint32_t Ks = base + Q_BYTES + (t & 1) * KV_STAGE_B;
        const uint32_t Vs = Ks + KV_TILE_B;

        // ---- S = Q @ K^T (software-pipelined fragments) ----
        float sacc[8][4];
        #pragma unroll
        for (int n = 0; n < 8; n++)
            #pragma unroll
            for (int i = 0; i < 4; i++) sacc[n][i] = 0.0f;

        uint32_t qf[2][4], kf[2][4];
        ldm_x4(qf[0][0], qf[0][1], qf[0][2], qf[0][3], Qs + lq_off * 2);
        ldm_x4(kf[0][0], kf[0][1], kf[0][2], kf[0][3], Ks + lk_off * 2);
        #pragma unroll
        for (int k16 = 0; k16 < 8; k16++) {
            const int qb = k16 & 1;
            #pragma unroll
            for (int ntp = 0; ntp < 4; ntp++) {
                const int s = k16 * 4 + ntp;
                const int cur = s & 1, nxt = cur ^ 1;
                if (s < 31) {
                    const int sn = s + 1;
                    const int k16n = sn >> 2, ntpn = sn & 3;
                    ldm_x4(kf[nxt][0], kf[nxt][1], kf[nxt][2], kf[nxt][3],
                           Ks + (lk_off + ntpn * 16 * FSTR + k16n * 16) * 2);
                }
                if (ntp == 0 && k16 < 7) {
                    ldm_x4(qf[qb ^ 1][0], qf[qb ^ 1][1], qf[qb ^ 1][2],
                           qf[qb ^ 1][3], Qs + (lq_off + (k16 + 1) * 16) * 2);
                }
                mma_f16(sacc[2 * ntp    ], qf[qb][0], qf[qb][1], qf[qb][2],
                        qf[qb][3], kf[cur][0], kf[cur][1]);
                mma_f16(sacc[2 * ntp + 1], qf[qb][0], qf[qb][1], qf[qb][2],
                        qf[qb][3], kf[cur][2], kf[cur][3]);
            }
        }

        // ---- causal mask (only last 2 tiles touch the diagonal) ----
        if (t >= ntile - 2) {
            const int j0 = t * 64;
            const int rg0 = q0 + mloc + qr;
            const int rg1 = rg0 + 8;
            #pragma unroll
            for (int nt = 0; nt < 8; nt++) {
                const int cg = j0 + nt * 8 + 2 * qc;
                if (cg     > rg0) sacc[nt][0] = -1.0e30f;
                if (cg + 1 > rg0) sacc[nt][1] = -1.0e30f;
                if (cg     > rg1) sacc[nt][2] = -1.0e30f;
                if (cg + 1 > rg1) sacc[nt][3] = -1.0e30f;
            }
        }

        // ---- online softmax (pre-scaled domain: exp args are subtracts) ----
        float mx0 = -3.0e38f, mx1 = -3.0e38f;
        #pragma unroll
        for (int nt = 0; nt < 8; nt++) {
            mx0 = fmaxf(mx0, fmaxf(sacc[nt][0], sacc[nt][1]));
            mx1 = fmaxf(mx1, fmaxf(sacc[nt][2], sacc[nt][3]));
        }
        mx0 = fmaxf(mx0, __shfl_xor_sync(0xFFFFFFFFu, mx0, 1));
        mx0 = fmaxf(mx0, __shfl_xor_sync(0xFFFFFFFFu, mx0, 2));
        mx1 = fmaxf(mx1, __shfl_xor_sync(0xFFFFFFFFu, mx1, 1));
        mx1 = fmaxf(mx1, __shfl_xor_sync(0xFFFFFFFFu, mx1, 2));
        const float pm0 = mrow0, pm1 = mrow1;
        const float mn0 = fmaxf(pm0, mx0);
        const float mn1 = fmaxf(pm1, mx1);
        const float al0 = __expf(pm0 - mn0);
        const float al1 = __expf(pm1 - mn1);
        mrow0 = mn0; mrow1 = mn1;

        float ps0 = 0.0f, ps1 = 0.0f;
        #pragma unroll
        for (int nt = 0; nt < 8; nt++) {
            sacc[nt][0] = __expf(sacc[nt][0] - mn0);
            sacc[nt][1] = __expf(sacc[nt][1] - mn0);
            sacc[nt][2] = __expf(sacc[nt][2] - mn1);
            sacc[nt][3] = __expf(sacc[nt][3] - mn1);
            ps0 += sacc[nt][0] + sacc[nt][1];
            ps1 += sacc[nt][2] + sacc[nt][3];
        }
        ps0 += __shfl_xor_sync(0xFFFFFFFFu, ps0, 1);
        ps0 += __shfl_xor_sync(0xFFFFFFFFu, ps0, 2);
        ps1 += __shfl_xor_sync(0xFFFFFFFFu, ps1, 1);
        ps1 += __shfl_xor_sync(0xFFFFFFFFu, ps1, 2);
        lrow0 = lrow0 * al0 + ps0;
        lrow1 = lrow1 * al1 + ps1;

        // rescale only if ANY lane's row-max moved (warp-uniform branch)
        if (__any_sync(0xFFFFFFFFu, (mn0 > pm0) || (mn1 > pm1))) {
            #pragma unroll
            for (int n = 0; n < 16; n++) {
                oacc[n][0] *= al0; oacc[n][1] *= al0;
                oacc[n][2] *= al1; oacc[n][3] *= al1;
            }
        }

        // ---- P fragments: direct pack (C-layout == A-layout in fp16) ----
        uint32_t pA[4][4];
        #pragma unroll
        for (int j = 0; j < 4; j++) {
            pA[j][0] = pack_h2(sacc[2 * j][0],     sacc[2 * j][1]);
            pA[j][1] = pack_h2(sacc[2 * j][2],     sacc[2 * j][3]);
            pA[j][2] = pack_h2(sacc[2 * j + 1][0], sacc[2 * j + 1][1]);
            pA[j][3] = pack_h2(sacc[2 * j + 1][2], sacc[2 * j + 1][3]);
        }

        // ---- O += P @ V (software-pipelined V fragments) ----
        uint32_t vf[2][4];
        ldm_x4_t(vf[0][0], vf[0][1], vf[0][2], vf[0][3], Vs + lv_off * 2);
        #pragma unroll
        for (int j = 0; j < 4; j++) {
            #pragma unroll
            for (int ntp = 0; ntp < 8; ntp++) {
                const int s = j * 8 + ntp;
                const int cur = s & 1, nxt = cur ^ 1;
                if (s < 31) {
                    const int sn = s + 1;
                    const int jn = sn >> 3, ntpn = sn & 7;
                    ldm_x4_t(vf[nxt][0], vf[nxt][1], vf[nxt][2], vf[nxt][3],
                             Vs + (lv_off + jn * 16 * FSTR + ntpn * 16) * 2);
                }
                mma_f16(oacc[2 * ntp    ], pA[j][0], pA[j][1], pA[j][2],
                        pA[j][3], vf[cur][0], vf[cur][1]);
                mma_f16(oacc[2 * ntp + 1], pA[j][0], pA[j][1], pA[j][2],
                        pA[j][3], vf[cur][2], vf[cur][3]);
            }
        }

        __syncthreads();
        if (t + 2 < ntile) {
            uint32_t sb = base + Q_BYTES + (t & 1) * KV_STAGE_B;
            load_kv_tile(sb, sb + KV_TILE_B, rowbase, (t + 2) * 64, qcol, tid);
        }
        cp_commit();
    }

    // ---- epilogue: normalize, fp16 store (feeds out-proj GEMM) ----
    const float li0 = 1.0f / lrow0;
    const float li1 = 1.0f / lrow1;
    const int r0 = q0 + mloc + qr;
    const int r1 = r0 + 8;
    #pragma unroll
    for (int ntd = 0; ntd < 16; ntd++) {
        const int col = qcol + ntd * 8 + 2 * qc;
        *(uint32_t*)&g_o[(rowbase + r0) * (size_t)D_ + col] =
            pack_h2(oacc[ntd][0] * li0, oacc[ntd][1] * li0);
        *(uint32_t*)&g_o[(rowbase + r1) * (size_t)D_ + col] =
            pack_h2(oacc[ntd][2] * li1, oacc[ntd][3] * li1);
    }
}

// ---------------------------------------------------------------------------
// Launch
// ---------------------------------------------------------------------------
extern "C" void kernel_launch(void* const* d_in, const int* in_sizes, int n_in,
                              void* d_out, int out_size)
{
    (void)in_sizes; (void)n_in; (void)out_size;
    const float* x    = (const float*)d_in[0];
    const float* Wqkv = (const float*)d_in[1];
    const float* bqkv = (const float*)d_in[2];
    const float* Wout = (const float*)d_in[3];
    const float* bout = (const float*)d_in[4];
    float* out = (float*)d_out;

    static __half *qkv_ptr = nullptr, *o_ptr = nullptr, *xh_ptr = nullptr;
    static __half *wqkvT_ptr = nullptr, *woutT_ptr = nullptr;
    static bool init_done = false;
    if (!init_done) {
        // First call is the (uncaptured) correctness run; these immediate host
        // APIs never land inside graph capture.
        cudaFuncSetAttribute(flash_mma_kernel,
                             cudaFuncAttributeMaxDynamicSharedMemorySize,
                             FLASH_SMEM);
        cudaFuncSetAttribute(mma_gemm_bias<true, true>,
                             cudaFuncAttributeMaxDynamicSharedMemorySize,
                             GEMM_SMEM);
        cudaFuncSetAttribute(mma_gemm_bias<false, false>,
                             cudaFuncAttributeMaxDynamicSharedMemorySize,
                             GEMM_SMEM);
        void* p;
        cudaGetSymbolAddress(&p, g_qkv);   qkv_ptr   = (__half*)p;
        cudaGetSymbolAddress(&p, g_o);     o_ptr     = (__half*)p;
        cudaGetSymbolAddress(&p, g_xh);    xh_ptr    = (__half*)p;
        cudaGetSymbolAddress(&p, g_WqkvT); wqkvT_ptr = (__half*)p;
        cudaGetSymbolAddress(&p, g_WoutT); woutT_ptr = (__half*)p;
        init_done = true;
    }

    // 0) pre-pass: x -> fp16; weights -> transposed fp16 [N,K]
    f2h_kernel<<<(MROWS * (size_t)D_ / 8) / 256, 256>>>(x, xh_ptr);
    transpose_kernel<<<dim3(QKV_N / 64, D_ / 64), 256>>>(Wqkv, wqkvT_ptr, D_, QKV_N);
    transpose_kernel<<<dim3(D_ / 64, D_ / 64), 256>>>(Wout, woutT_ptr, D_, D_);

    // 1) QKV = x @ Wqkv + bqkv (fp16 mma; Q block pre-scaled by 1/sqrt(Dh))
    mma_gemm_bias<true, true><<<dim3(QKV_N / GBN, MROWS / GBM), 256, GEMM_SMEM>>>(
        xh_ptr, wqkvT_ptr, bqkv, qkv_ptr, MROWS, QKV_N, D_);

    // 2) causal flash attention (fp16 tensor cores) -> g_o (fp16)
    flash_mma_kernel<<<dim3(T_ / FBQ, H_, B_), 256, FLASH_SMEM>>>();

    // 3) out = g_o @ Wout + bout (fp16 mma, fp32 output)
    mma_gemm_bias<false, false><<<dim3(D_ / GBN, MROWS / GBM), 256, GEMM_SMEM>>>(
        o_ptr, woutT_ptr, bout, out, MROWS, D_, D_);
}

// round 15
// speedup vs baseline: 1.0075x; 1.0075x over previous
#include <cuda_runtime.h>
#include <cuda_fp16.h>
#include <math.h>
#include <stdint.h>

#define B_  2
#define T_  2048
#define D_  2048
#define H_  16
#define DH  128
#define MROWS (B_*T_)          // 4096
#define QKV_N (3*D_)           // 6144

// Scratch (device globals — no allocation allowed); all fp16 operands
__device__ __half g_qkv[(size_t)MROWS * QKV_N];    // 50 MB (Q pre-scaled by s*log2e)
__device__ __half g_o[(size_t)MROWS * D_];         // 16 MB
__device__ __half g_xh[(size_t)MROWS * D_];        // 16 MB
__device__ __half g_WqkvT[(size_t)QKV_N * D_];     // 25 MB ([N,K] K-contig)
__device__ __half g_WoutT[(size_t)D_ * D_];        // 8 MB

// softmax runs in the log2 domain: Q pre-scaled by (1/sqrt(Dh)) * log2(e)
#define QSCALE 0.12751744416349243f

// ---------------------------------------------------------------------------
// Helpers
// ---------------------------------------------------------------------------
__device__ __forceinline__ void cp_async16(uint32_t s, const void* g) {
    asm volatile("cp.async.cg.shared.global [%0], [%1], 16;" :: "r"(s), "l"(g));
}
__device__ __forceinline__ void cp_commit() {
    asm volatile("cp.async.commit_group;" ::: "memory");
}
template <int N> __device__ __forceinline__ void cp_wait() {
    asm volatile("cp.async.wait_group %0;" :: "n"(N) : "memory");
}
__device__ __forceinline__ uint32_t smem_u32(const void* p) {
    uint32_t a;
    asm("{ .reg .u64 t; cvta.to.shared.u64 t, %1; cvt.u32.u64 %0, t; }"
        : "=r"(a) : "l"(p));
    return a;
}
__device__ __forceinline__ void ldm_x4(uint32_t& r0, uint32_t& r1,
                                       uint32_t& r2, uint32_t& r3, uint32_t a) {
    asm volatile("ldmatrix.sync.aligned.m8n8.x4.shared.b16 {%0,%1,%2,%3}, [%4];"
                 : "=r"(r0), "=r"(r1), "=r"(r2), "=r"(r3) : "r"(a));
}
__device__ __forceinline__ void ldm_x4_t(uint32_t& r0, uint32_t& r1,
                                         uint32_t& r2, uint32_t& r3, uint32_t a) {
    asm volatile("ldmatrix.sync.aligned.m8n8.x4.trans.shared.b16 {%0,%1,%2,%3}, [%4];"
                 : "=r"(r0), "=r"(r1), "=r"(r2), "=r"(r3) : "r"(a));
}
__device__ __forceinline__ void mma_f16(float c[4],
    uint32_t a0, uint32_t a1, uint32_t a2, uint32_t a3,
    uint32_t b0, uint32_t b1)
{
    asm volatile(
        "mma.sync.aligned.m16n8k16.row.col.f32.f16.f16.f32 "
        "{%0,%1,%2,%3}, {%4,%5,%6,%7}, {%8,%9}, {%0,%1,%2,%3};"
        : "+f"(c[0]), "+f"(c[1]), "+f"(c[2]), "+f"(c[3])
        : "r"(a0), "r"(a1), "r"(a2), "r"(a3), "r"(b0), "r"(b1));
}
__device__ __forceinline__ uint32_t pack_h2(float x, float y) {
    __half2 h = __floats2half2_rn(x, y);
    return *(uint32_t*)&h;
}
__device__ __forceinline__ float fexp2(float x) {
    float r;
    asm("ex2.approx.f32 %0, %1;" : "=f"(r) : "f"(x));
    return r;
}

// ---------------------------------------------------------------------------
// x pre-pass: fp32 -> fp16. Each thread converts 8 floats.
// ---------------------------------------------------------------------------
__global__ __launch_bounds__(256) void f2h_kernel(
    const float* __restrict__ in, __half* __restrict__ out)
{
    const size_t i = (size_t)blockIdx.x * 256 + threadIdx.x;
    float4 a = ((const float4*)in)[2 * i];
    float4 b = ((const float4*)in)[2 * i + 1];
    uint4 u;
    u.x = pack_h2(a.x, a.y); u.y = pack_h2(a.z, a.w);
    u.z = pack_h2(b.x, b.y); u.w = pack_h2(b.z, b.w);
    ((uint4*)out)[i] = u;
}

// ---------------------------------------------------------------------------
// Weight transpose + fp16: At[C, R] = h(A[R, C]^T), k(=R) contiguous in At.
// 64x64 tiles; float4 gmem reads, fp16 smem staging, uint4 coalesced stores.
// ---------------------------------------------------------------------------
__global__ __launch_bounds__(256) void transpose_kernel(
    const float* __restrict__ A, __half* __restrict__ At, int R, int C)
{
    __shared__ __half tile[64][72];
    const int k0 = blockIdx.y * 64;
    const int n0 = blockIdx.x * 64;
    const int tid = threadIdx.x;

    #pragma unroll
    for (int i = 0; i < 4; i++) {
        int idx = tid + i * 256;
        int r = idx >> 4;
        int c4 = (idx & 15) * 4;
        float4 v = *(const float4*)&A[(size_t)(k0 + r) * C + n0 + c4];
        tile[c4 + 0][r] = __float2half_rn(v.x);
        tile[c4 + 1][r] = __float2half_rn(v.y);
        tile[c4 + 2][r] = __float2half_rn(v.z);
        tile[c4 + 3][r] = __float2half_rn(v.w);
    }
    __syncthreads();

    #pragma unroll
    for (int i = 0; i < 2; i++) {
        int idx = tid + i * 256;
        int n = idx >> 3;
        int k8 = (idx & 7) * 8;
        *(uint4*)&At[(size_t)(n0 + n) * R + k0 + k8] = *(uint4*)&tile[n][k8];
    }
}

// ---------------------------------------------------------------------------
// fp16 mma.sync GEMM + bias (R12 core): CTA 128x256, 8 warps, warp tile
// 64x64, 4-stage depth-3 cp.async pipeline, fragment double-buffering,
// rotated stage boundary. 1 CTA/SM (254 regs).
// SCALE_Q: Q block (cols < D_) scaled by QSCALE for log2-domain softmax.
// ---------------------------------------------------------------------------
#define GBM 128
#define GBN 256
#define GBK 64
#define STRH 72
#define A_TILE_H (128 * STRH)                 // 9216 halves
#define B_TILE_H (256 * STRH)                 // 18432 halves
#define STAGE_B  ((A_TILE_H + B_TILE_H) * 2)  // 55296 bytes
#define GSTAGES  4
#define GEMM_SMEM (GSTAGES * STAGE_B)         // 221184

__device__ __forceinline__ void gemm_load_stage(
    const __half* __restrict__ A, const __half* __restrict__ BT, int K,
    uint32_t sa, uint32_t sb, int brow, int bcol, int k0, int tid)
{
    #pragma unroll
    for (int i = 0; i < 4; i++) {           // A: 128 rows x 8 chunks
        int idx = tid + i * 256;
        int row = idx >> 3;
        int c = idx & 7;
        cp_async16(sa + (row * STRH + c * 8) * 2,
                   &A[(size_t)(brow + row) * K + k0 + c * 8]);
    }
    #pragma unroll
    for (int i = 0; i < 8; i++) {           // B^T: 256 n-rows x 8 chunks
        int idx = tid + i * 256;
        int row = idx >> 3;
        int c = idx & 7;
        cp_async16(sb + (row * STRH + c * 8) * 2,
                   &BT[(size_t)(bcol + row) * K + k0 + c * 8]);
    }
}

#define LOAD_FRAGS(FA, FB, sa, sb, ko)                                        \
    do {                                                                      \
        ldm_x4((FA)[0],  (FA)[1],  (FA)[2],  (FA)[3],                         \
               (sa) + (la_off + (ko)) * 2);                                   \
        ldm_x4((FA)[4],  (FA)[5],  (FA)[6],  (FA)[7],                         \
               (sa) + (la_off + 16 * STRH + (ko)) * 2);                       \
        ldm_x4((FA)[8],  (FA)[9],  (FA)[10], (FA)[11],                        \
               (sa) + (la_off + 32 * STRH + (ko)) * 2);                       \
        ldm_x4((FA)[12], (FA)[13], (FA)[14], (FA)[15],                        \
               (sa) + (la_off + 48 * STRH + (ko)) * 2);                       \
        ldm_x4((FB)[0],  (FB)[1],  (FB)[2],  (FB)[3],                         \
               (sb) + (lb_off + (ko)) * 2);                                   \
        ldm_x4((FB)[4],  (FB)[5],  (FB)[6],  (FB)[7],                         \
               (sb) + (lb_off + 16 * STRH + (ko)) * 2);                       \
        ldm_x4((FB)[8],  (FB)[9],  (FB)[10], (FB)[11],                        \
               (sb) + (lb_off + 32 * STRH + (ko)) * 2);                       \
        ldm_x4((FB)[12], (FB)[13], (FB)[14], (FB)[15],                        \
               (sb) + (lb_off + 48 * STRH + (ko)) * 2);                       \
    } while (0)

#define MMA_BLOCK(cur)                                                        \
    do {                                                                      \
        _Pragma("unroll")                                                     \
        for (int j = 0; j < 4; j++) {                                         \
            _Pragma("unroll")                                                 \
            for (int i = 0; i < 4; i++) {                                     \
                mma_f16(acc[i][2 * j],                                        \
                        fa[cur][4 * i], fa[cur][4 * i + 1],                   \
                        fa[cur][4 * i + 2], fa[cur][4 * i + 3],               \
                        fb[cur][4 * j], fb[cur][4 * j + 1]);                  \
                mma_f16(acc[i][2 * j + 1],                                    \
                        fa[cur][4 * i], fa[cur][4 * i + 1],                   \
                        fa[cur][4 * i + 2], fa[cur][4 * i + 3],               \
                        fb[cur][4 * j + 2], fb[cur][4 * j + 3]);              \
            }                                                                 \
        }                                                                     \
    } while (0)

template <bool OUT_HALF, bool SCALE_Q>
__global__ __launch_bounds__(256, 1) void mma_gemm_bias(
    const __half* __restrict__ A, const __half* __restrict__ BT,
    const float* __restrict__ bias, void* __restrict__ Cv,
    int M, int N, int K)
{
    extern __shared__ char sm[];
    const int tid  = threadIdx.x;
    const int wid  = tid >> 5;
    const int lane = tid & 31;
    const int brow = blockIdx.y * GBM;
    const int bcol = blockIdx.x * GBN;
    const int warp_m = wid & 1;
    const int warp_n = wid >> 1;
    const int qr = lane >> 2;
    const int qc = lane & 3;

    const uint32_t base = smem_u32(sm);

    float acc[4][8][4];
    #pragma unroll
    for (int mt = 0; mt < 4; mt++)
        #pragma unroll
        for (int nt = 0; nt < 8; nt++)
            #pragma unroll
            for (int i = 0; i < 4; i++)
                acc[mt][nt][i] = 0.0f;

    const int KT = K / GBK;   // 32

    #pragma unroll
    for (int s = 0; s < 3; s++) {
        const uint32_t sa = base + s * STAGE_B;
        gemm_load_stage(A, BT, K, sa, sa + A_TILE_H * 2, brow, bcol,
                        s * GBK, tid);
        cp_commit();
    }

    const int la_off = (warp_m * 64 + (lane & 15)) * STRH + (lane >> 4) * 8;
    const int g = lane >> 3;
    const int lb_off = (warp_n * 64 + ((g & 2) ? 8 : 0) + (lane & 7)) * STRH
                     + (g & 1) * 8;

    uint32_t fa[2][16], fb[2][16];

    cp_wait<2>();
    __syncthreads();
    LOAD_FRAGS(fa[0], fb[0], base, base + A_TILE_H * 2, 0);

    int st = 0;
    for (int kt = 0; kt < KT; kt++) {
        const int lkt = kt + 3;
        if (lkt < KT) {
            int fst = st + 3; if (fst >= GSTAGES) fst -= GSTAGES;
            const uint32_t pa = base + fst * STAGE_B;
            gemm_load_stage(A, BT, K, pa, pa + A_TILE_H * 2, brow, bcol,
                            lkt * GBK, tid);
        }
        cp_commit();

        const uint32_t sa = base + st * STAGE_B;
        const uint32_t sb = sa + A_TILE_H * 2;

        #pragma unroll
        for (int k16 = 0; k16 < 3; k16++) {
            const int cur = k16 & 1, nxt = cur ^ 1;
            LOAD_FRAGS(fa[nxt], fb[nxt], sa, sb, (k16 + 1) * 16);
            MMA_BLOCK(cur);
        }

        cp_wait<2>();
        __syncthreads();
        int nst = st + 1; if (nst >= GSTAGES) nst -= GSTAGES;
        if (kt + 1 < KT) {
            const uint32_t na = base + nst * STAGE_B;
            LOAD_FRAGS(fa[0], fb[0], na, na + A_TILE_H * 2, 0);
        }
        MMA_BLOCK(1);
        st = nst;
    }

    #pragma unroll
    for (int mt = 0; mt < 4; mt++) {
        const int row0 = brow + warp_m * 64 + mt * 16 + qr;
        #pragma unroll
        for (int nt = 0; nt < 8; nt++) {
            const int col = bcol + warp_n * 64 + nt * 8 + 2 * qc;
            const float2 bb = *(const float2*)&bias[col];
            float vx = acc[mt][nt][0] + bb.x;
            float vy = acc[mt][nt][1] + bb.y;
            float wx = acc[mt][nt][2] + bb.x;
            float wy = acc[mt][nt][3] + bb.y;
            if (SCALE_Q && col < D_) {   // Q block: scale for log2 softmax
                vx *= QSCALE; vy *= QSCALE;
                wx *= QSCALE; wy *= QSCALE;
            }
            if (OUT_HALF) {
                __half* C = (__half*)Cv;
                *(uint32_t*)&C[(size_t)row0 * N + col]       = pack_h2(vx, vy);
                *(uint32_t*)&C[(size_t)(row0 + 8) * N + col] = pack_h2(wx, wy);
            } else {
                float* C = (float*)Cv;
                float2 o0; o0.x = vx; o0.y = vy;
                float2 o1; o1.x = wx; o1.y = wy;
                *(float2*)&C[(size_t)row0 * N + col]       = o0;
                *(float2*)&C[(size_t)(row0 + 8) * N + col] = o1;
            }
        }
    }
}

// ---------------------------------------------------------------------------
// fp16 tensor-core flash attention (causal, log2-domain register softmax).
// Q arrives pre-scaled by (1/sqrt(Dh))*log2e -> exp2(sub) only.
// Fused exp->P-pack keeps register peak under the 128-reg 2-CTA/SM cliff.
// CTA: 128 q-rows, 256 threads. KV tiles of 64, double-buffered cp.async.
// Row stride 136 halves. S/PV fragments software-pipelined.
// ---------------------------------------------------------------------------
#define FBQ   128
#define FSTR  136
#define Q_BYTES     (128 * FSTR * 2)          // 34816
#define KV_TILE_B   (64 * FSTR * 2)           // 17408
#define KV_STAGE_B  (2 * KV_TILE_B)           // 34816
#define FLASH_SMEM  (Q_BYTES + 2 * KV_STAGE_B)  // 104448

__device__ __forceinline__ void load_kv_tile(
    uint32_t kbase, uint32_t vbase, size_t rowbase, int j0, int qcol, int tid)
{
    #pragma unroll
    for (int i = 0; i < 4; i++) {
        int idx = tid + i * 256;
        int r = idx >> 4;
        int c = idx & 15;
        cp_async16(kbase + (r * FSTR + c * 8) * 2,
                   &g_qkv[(rowbase + j0 + r) * (size_t)QKV_N + qcol + D_ + c * 8]);
    }
    #pragma unroll
    for (int i = 0; i < 4; i++) {
        int idx = tid + i * 256;
        int r = idx >> 4;
        int c = idx & 15;
        cp_async16(vbase + (r * FSTR + c * 8) * 2,
                   &g_qkv[(rowbase + j0 + r) * (size_t)QKV_N + qcol + 2 * D_ + c * 8]);
    }
}

__global__ __launch_bounds__(256, 2) void flash_mma_kernel()
{
    extern __shared__ char smc[];
    const int qi  = (gridDim.x - 1) - blockIdx.x;   // big q-blocks first
    const int q0  = qi * FBQ;
    const int h   = blockIdx.y;
    const int b   = blockIdx.z;
    const int tid = threadIdx.x;
    const int lane = tid & 31;
    const int wid  = tid >> 5;
    const int qr = lane >> 2;
    const int qc = lane & 3;

    const size_t rowbase = (size_t)b * T_;
    const int qcol = h * DH;

    const uint32_t base = smem_u32(smc);
    const uint32_t Qs = base;
    const int ntile = 2 * qi + 2;

    #pragma unroll
    for (int i = 0; i < 8; i++) {
        int idx = tid + i * 256;
        int r = idx >> 4;
        int c = idx & 15;
        cp_async16(Qs + (r * FSTR + c * 8) * 2,
                   &g_qkv[(rowbase + q0 + r) * (size_t)QKV_N + qcol + c * 8]);
    }
    {
        uint32_t s0 = base + Q_BYTES;
        load_kv_tile(s0, s0 + KV_TILE_B, rowbase, 0, qcol, tid);
        cp_commit();
        if (ntile > 1) {
            uint32_t s1 = base + Q_BYTES + KV_STAGE_B;
            load_kv_tile(s1, s1 + KV_TILE_B, rowbase, 64, qcol, tid);
        }
        cp_commit();
    }

    float oacc[16][4];
    #pragma unroll
    for (int n = 0; n < 16; n++)
        #pragma unroll
        for (int i = 0; i < 4; i++) oacc[n][i] = 0.0f;
    float mrow0 = -3.0e38f, mrow1 = -3.0e38f;
    float lrow0 = 0.0f, lrow1 = 0.0f;

    const int mloc = wid * 16;
    const int g = lane >> 3;
    const int lq_off = (mloc + (lane & 15)) * FSTR + (lane >> 4) * 8;
    const int lk_off = (((g & 2) ? 8 : 0) + (lane & 7)) * FSTR + (g & 1) * 8;
    const int lv_off = ((g & 1) * 8 + (lane & 7)) * FSTR + ((g & 2) ? 8 : 0);

    for (int t = 0; t < ntile; t++) {
        cp_wait<1>();
        __syncthreads();

        const uint32_t Ks = base + Q_BYTES + (t & 1) * KV_STAGE_B;
        const uint32_t Vs = Ks + KV_TILE_B;

        // ---- S = Q @ K^T (software-pipelined fragments) ----
        float sacc[8][4];
        #pragma unroll
        for (int n = 0; n < 8; n++)
            #pragma unroll
            for (int i = 0; i < 4; i++) sacc[n][i] = 0.0f;

        uint32_t qf[2][4], kf[2][4];
        ldm_x4(qf[0][0], qf[0][1], qf[0][2], qf[0][3], Qs + lq_off * 2);
        ldm_x4(kf[0][0], kf[0][1], kf[0][2], kf[0][3], Ks + lk_off * 2);
        #pragma unroll
        for (int k16 = 0; k16 < 8; k16++) {
            const int qb = k16 & 1;
            #pragma unroll
            for (int ntp = 0; ntp < 4; ntp++) {
                const int s = k16 * 4 + ntp;
                const int cur = s & 1, nxt = cur ^ 1;
                if (s < 31) {
                    const int sn = s + 1;
                    const int k16n = sn >> 2, ntpn = sn & 3;
                    ldm_x4(kf[nxt][0], kf[nxt][1], kf[nxt][2], kf[nxt][3],
                           Ks + (lk_off + ntpn * 16 * FSTR + k16n * 16) * 2);
                }
                if (ntp == 0 && k16 < 7) {
                    ldm_x4(qf[qb ^ 1][0], qf[qb ^ 1][1], qf[qb ^ 1][2],
                           qf[qb ^ 1][3], Qs + (lq_off + (k16 + 1) * 16) * 2);
                }
                mma_f16(sacc[2 * ntp    ], qf[qb][0], qf[qb][1], qf[qb][2],
                        qf[qb][3], kf[cur][0], kf[cur][1]);
                mma_f16(sacc[2 * ntp + 1], qf[qb][0], qf[qb][1], qf[qb][2],
                        qf[qb][3], kf[cur][2], kf[cur][3]);
            }
        }

        // ---- causal mask (only last 2 tiles touch the diagonal) ----
        if (t >= ntile - 2) {
            const int j0 = t * 64;
            const int rg0 = q0 + mloc + qr;
            const int rg1 = rg0 + 8;
            #pragma unroll
            for (int nt = 0; nt < 8; nt++) {
                const int cg = j0 + nt * 8 + 2 * qc;
                if (cg     > rg0) sacc[nt][0] = -1.0e30f;
                if (cg + 1 > rg0) sacc[nt][1] = -1.0e30f;
                if (cg     > rg1) sacc[nt][2] = -1.0e30f;
                if (cg + 1 > rg1) sacc[nt][3] = -1.0e30f;
            }
        }

        // ---- online softmax (log2 domain; exp2 of plain subtract) ----
        float mx0 = -3.0e38f, mx1 = -3.0e38f;
        #pragma unroll
        for (int nt = 0; nt < 8; nt++) {
            mx0 = fmaxf(mx0, fmaxf(sacc[nt][0], sacc[nt][1]));
            mx1 = fmaxf(mx1, fmaxf(sacc[nt][2], sacc[nt][3]));
        }
        mx0 = fmaxf(mx0, __shfl_xor_sync(0xFFFFFFFFu, mx0, 1));
        mx0 = fmaxf(mx0, __shfl_xor_sync(0xFFFFFFFFu, mx0, 2));
        mx1 = fmaxf(mx1, __shfl_xor_sync(0xFFFFFFFFu, mx1, 1));
        mx1 = fmaxf(mx1, __shfl_xor_sync(0xFFFFFFFFu, mx1, 2));
        const float mn0 = fmaxf(mrow0, mx0);
        const float mn1 = fmaxf(mrow1, mx1);
        const float al0 = fexp2(mrow0 - mn0);
        const float al1 = fexp2(mrow1 - mn1);
        mrow0 = mn0; mrow1 = mn1;

        // fused exp -> P-pack (sacc dies as pA is born: lower register peak)
        uint32_t pA[4][4];
        float ps0 = 0.0f, ps1 = 0.0f;
        #pragma unroll
        for (int j = 0; j < 4; j++) {
            float e00 = fexp2(sacc[2 * j][0] - mn0);
            float e01 = fexp2(sacc[2 * j][1] - mn0);
            float e02 = fexp2(sacc[2 * j][2] - mn1);
            float e03 = fexp2(sacc[2 * j][3] - mn1);
            float e10 = fexp2(sacc[2 * j + 1][0] - mn0);
            float e11 = fexp2(sacc[2 * j + 1][1] - mn0);
            float e12 = fexp2(sacc[2 * j + 1][2] - mn1);
            float e13 = fexp2(sacc[2 * j + 1][3] - mn1);
            ps0 += (e00 + e01) + (e10 + e11);
            ps1 += (e02 + e03) + (e12 + e13);
            pA[j][0] = pack_h2(e00, e01);
            pA[j][1] = pack_h2(e02, e03);
            pA[j][2] = pack_h2(e10, e11);
            pA[j][3] = pack_h2(e12, e13);
        }
        ps0 += __shfl_xor_sync(0xFFFFFFFFu, ps0, 1);
        ps0 += __shfl_xor_sync(0xFFFFFFFFu, ps0, 2);
        ps1 += __shfl_xor_sync(0xFFFFFFFFu, ps1, 1);
        ps1 += __shfl_xor_sync(0xFFFFFFFFu, ps1, 2);
        lrow0 = lrow0 * al0 + ps0;
        lrow1 = lrow1 * al1 + ps1;

        #pragma unroll
        for (int n = 0; n < 16; n++) {
            oacc[n][0] *= al0; oacc[n][1] *= al0;
            oacc[n][2] *= al1; oacc[n][3] *= al1;
        }

        // ---- O += P @ V (software-pipelined V fragments) ----
        uint32_t vf[2][4];
        ldm_x4_t(vf[0][0], vf[0][1], vf[0][2], vf[0][3], Vs + lv_off * 2);
        #pragma unroll
        for (int j = 0; j < 4; j++) {
            #pragma unroll
            for (int ntp = 0; ntp < 8; ntp++) {
                const int s = j * 8 + ntp;
                const int cur = s & 1, nxt = cur ^ 1;
                if (s < 31) {
                    const int sn = s + 1;
                    const int jn = sn >> 3, ntpn = sn & 7;
                    ldm_x4_t(vf[nxt][0], vf[nxt][1], vf[nxt][2], vf[nxt][3],
                             Vs + (lv_off + jn * 16 * FSTR + ntpn * 16) * 2);
                }
                mma_f16(oacc[2 * ntp    ], pA[j][0], pA[j][1], pA[j][2],
                        pA[j][3], vf[cur][0], vf[cur][1]);
                mma_f16(oacc[2 * ntp + 1], pA[j][0], pA[j][1], pA[j][2],
                        pA[j][3], vf[cur][2], vf[cur][3]);
            }
        }

        __syncthreads();
        if (t + 2 < ntile) {
            uint32_t sb = base + Q_BYTES + (t & 1) * KV_STAGE_B;
            load_kv_tile(sb, sb + KV_TILE_B, rowbase, (t + 2) * 64, qcol, tid);
        }
        cp_commit();
    }

    // ---- epilogue: normalize, fp16 store (feeds out-proj GEMM) ----
    const float li0 = 1.0f / lrow0;
    const float li1 = 1.0f / lrow1;
    const int r0 = q0 + mloc + qr;
    const int r1 = r0 + 8;
    #pragma unroll
    for (int ntd = 0; ntd < 16; ntd++) {
        const int col = qcol + ntd * 8 + 2 * qc;
        *(uint32_t*)&g_o[(rowbase + r0) * (size_t)D_ + col] =
            pack_h2(oacc[ntd][0] * li0, oacc[ntd][1] * li0);
        *(uint32_t*)&g_o[(rowbase + r1) * (size_t)D_ + col] =
            pack_h2(oacc[ntd][2] * li1, oacc[ntd][3] * li1);
    }
}

// ---------------------------------------------------------------------------
// Launch
// ---------------------------------------------------------------------------
extern "C" void kernel_launch(void* const* d_in, const int* in_sizes, int n_in,
                              void* d_out, int out_size)
{
    (void)in_sizes; (void)n_in; (void)out_size;
    const float* x    = (const float*)d_in[0];
    const float* Wqkv = (const float*)d_in[1];
    const float* bqkv = (const float*)d_in[2];
    const float* Wout = (const float*)d_in[3];
    const float* bout = (const float*)d_in[4];
    float* out = (float*)d_out;

    static __half *qkv_ptr = nullptr, *o_ptr = nullptr, *xh_ptr = nullptr;
    static __half *wqkvT_ptr = nullptr, *woutT_ptr = nullptr;
    static bool init_done = false;
    if (!init_done) {
        // First call is the (uncaptured) correctness run; these immediate host
        // APIs never land inside graph capture.
        cudaFuncSetAttribute(flash_mma_kernel,
                             cudaFuncAttributeMaxDynamicSharedMemorySize,
                             FLASH_SMEM);
        cudaFuncSetAttribute(mma_gemm_bias<true, true>,
                             cudaFuncAttributeMaxDynamicSharedMemorySize,
                             GEMM_SMEM);
        cudaFuncSetAttribute(mma_gemm_bias<false, false>,
                             cudaFuncAttributeMaxDynamicSharedMemorySize,
                             GEMM_SMEM);
        void* p;
        cudaGetSymbolAddress(&p, g_qkv);   qkv_ptr   = (__half*)p;
        cudaGetSymbolAddress(&p, g_o);     o_ptr     = (__half*)p;
        cudaGetSymbolAddress(&p, g_xh);    xh_ptr    = (__half*)p;
        cudaGetSymbolAddress(&p, g_WqkvT); wqkvT_ptr = (__half*)p;
        cudaGetSymbolAddress(&p, g_WoutT); woutT_ptr = (__half*)p;
        init_done = true;
    }

    // 0) pre-pass: x -> fp16; weights -> transposed fp16 [N,K]
    f2h_kernel<<<(MROWS * (size_t)D_ / 8) / 256, 256>>>(x, xh_ptr);
    transpose_kernel<<<dim3(QKV_N / 64, D_ / 64), 256>>>(Wqkv, wqkvT_ptr, D_, QKV_N);
    transpose_kernel<<<dim3(D_ / 64, D_ / 64), 256>>>(Wout, woutT_ptr, D_, D_);

    // 1) QKV = x @ Wqkv + bqkv (fp16 mma; Q pre-scaled by s*log2e)
    mma_gemm_bias<true, true><<<dim3(QKV_N / GBN, MROWS / GBM), 256, GEMM_SMEM>>>(
        xh_ptr, wqkvT_ptr, bqkv, qkv_ptr, MROWS, QKV_N, D_);

    // 2) causal flash attention (fp16 tensor cores) -> g_o (fp16)
    flash_mma_kernel<<<dim3(T_ / FBQ, H_, B_), 256, FLASH_SMEM>>>();

    // 3) out = g_o @ Wout + bout (fp16 mma, fp32 output)
    mma_gemm_bias<false, false><<<dim3(D_ / GBN, MROWS / GBM), 256, GEMM_SMEM>>>(
        o_ptr, woutT_ptr, bout, out, MROWS, D_, D_);
}

// round 16
// speedup vs baseline: 1.0160x; 1.0085x over previous
#include <cuda_runtime.h>
#include <cuda_fp16.h>
#include <math.h>
#include <stdint.h>

#define B_  2
#define T_  2048
#define D_  2048
#define H_  16
#define DH  128
#define MROWS (B_*T_)          // 4096
#define QKV_N (3*D_)           // 6144

// Scratch (device globals — no allocation allowed); all fp16 operands
__device__ __half g_qkv[(size_t)MROWS * QKV_N];    // 50 MB (Q pre-scaled by s*log2e)
__device__ __half g_o[(size_t)MROWS * D_];         // 16 MB
__device__ __half g_xh[(size_t)MROWS * D_];        // 16 MB
__device__ __half g_WqkvT[(size_t)QKV_N * D_];     // 25 MB ([N,K] K-contig)
__device__ __half g_WoutT[(size_t)D_ * D_];        // 8 MB

// softmax runs in the log2 domain: Q pre-scaled by (1/sqrt(Dh)) * log2(e)
#define QSCALE 0.12751744416349243f

// ---------------------------------------------------------------------------
// Helpers
// ---------------------------------------------------------------------------
__device__ __forceinline__ void cp_async16(uint32_t s, const void* g) {
    asm volatile("cp.async.cg.shared.global [%0], [%1], 16;" :: "r"(s), "l"(g));
}
__device__ __forceinline__ void cp_commit() {
    asm volatile("cp.async.commit_group;" ::: "memory");
}
template <int N> __device__ __forceinline__ void cp_wait() {
    asm volatile("cp.async.wait_group %0;" :: "n"(N) : "memory");
}
__device__ __forceinline__ uint32_t smem_u32(const void* p) {
    uint32_t a;
    asm("{ .reg .u64 t; cvta.to.shared.u64 t, %1; cvt.u32.u64 %0, t; }"
        : "=r"(a) : "l"(p));
    return a;
}
__device__ __forceinline__ void ldm_x4(uint32_t& r0, uint32_t& r1,
                                       uint32_t& r2, uint32_t& r3, uint32_t a) {
    asm volatile("ldmatrix.sync.aligned.m8n8.x4.shared.b16 {%0,%1,%2,%3}, [%4];"
                 : "=r"(r0), "=r"(r1), "=r"(r2), "=r"(r3) : "r"(a));
}
__device__ __forceinline__ void ldm_x4_t(uint32_t& r0, uint32_t& r1,
                                         uint32_t& r2, uint32_t& r3, uint32_t a) {
    asm volatile("ldmatrix.sync.aligned.m8n8.x4.trans.shared.b16 {%0,%1,%2,%3}, [%4];"
                 : "=r"(r0), "=r"(r1), "=r"(r2), "=r"(r3) : "r"(a));
}
__device__ __forceinline__ void mma_f16(float c[4],
    uint32_t a0, uint32_t a1, uint32_t a2, uint32_t a3,
    uint32_t b0, uint32_t b1)
{
    asm volatile(
        "mma.sync.aligned.m16n8k16.row.col.f32.f16.f16.f32 "
        "{%0,%1,%2,%3}, {%4,%5,%6,%7}, {%8,%9}, {%0,%1,%2,%3};"
        : "+f"(c[0]), "+f"(c[1]), "+f"(c[2]), "+f"(c[3])
        : "r"(a0), "r"(a1), "r"(a2), "r"(a3), "r"(b0), "r"(b1));
}
__device__ __forceinline__ uint32_t pack_h2(float x, float y) {
    __half2 h = __floats2half2_rn(x, y);
    return *(uint32_t*)&h;
}
__device__ __forceinline__ float fexp2(float x) {
    float r;
    asm("ex2.approx.f32 %0, %1;" : "=f"(r) : "f"(x));
    return r;
}

// ---------------------------------------------------------------------------
// x pre-pass: fp32 -> fp16. Each thread converts 8 floats.
// ---------------------------------------------------------------------------
__global__ __launch_bounds__(256) void f2h_kernel(
    const float* __restrict__ in, __half* __restrict__ out)
{
    const size_t i = (size_t)blockIdx.x * 256 + threadIdx.x;
    float4 a = ((const float4*)in)[2 * i];
    float4 b = ((const float4*)in)[2 * i + 1];
    uint4 u;
    u.x = pack_h2(a.x, a.y); u.y = pack_h2(a.z, a.w);
    u.z = pack_h2(b.x, b.y); u.w = pack_h2(b.z, b.w);
    ((uint4*)out)[i] = u;
}

// ---------------------------------------------------------------------------
// Weight transpose + fp16: At[C, R] = h(A[R, C]^T), k(=R) contiguous in At.
// 64x64 tiles; float4 gmem reads, fp16 smem staging, uint4 coalesced stores.
// ---------------------------------------------------------------------------
__global__ __launch_bounds__(256) void transpose_kernel(
    const float* __restrict__ A, __half* __restrict__ At, int R, int C)
{
    __shared__ __half tile[64][72];
    const int k0 = blockIdx.y * 64;
    const int n0 = blockIdx.x * 64;
    const int tid = threadIdx.x;

    #pragma unroll
    for (int i = 0; i < 4; i++) {
        int idx = tid + i * 256;
        int r = idx >> 4;
        int c4 = (idx & 15) * 4;
        float4 v = *(const float4*)&A[(size_t)(k0 + r) * C + n0 + c4];
        tile[c4 + 0][r] = __float2half_rn(v.x);
        tile[c4 + 1][r] = __float2half_rn(v.y);
        tile[c4 + 2][r] = __float2half_rn(v.z);
        tile[c4 + 3][r] = __float2half_rn(v.w);
    }
    __syncthreads();

    #pragma unroll
    for (int i = 0; i < 2; i++) {
        int idx = tid + i * 256;
        int n = idx >> 3;
        int k8 = (idx & 7) * 8;
        *(uint4*)&At[(size_t)(n0 + n) * R + k0 + k8] = *(uint4*)&tile[n][k8];
    }
}

// ---------------------------------------------------------------------------
// fp16 mma.sync GEMM + bias: CTA 128x128, 128 threads (4 warps, 2m x 2n),
// warp tile 64x64 (keeps the low 128 B/MMA crossbar load of R12) with
// 2 CTAs/SM (barrier decoupling: one CTA's stage-boundary convoy overlaps
// the other's MMA phase — the R7 mechanism). 3-stage depth-2 cp.async
// pipeline, register fragment double-buffering, rotated stage boundary.
// Budget: 254 regs x 128thr x 2 = 65024 <= 64K regfile; smem 110592 x 2.
// ---------------------------------------------------------------------------
#define GBM 128
#define GBN 128
#define GBK 64
#define STRH 72
#define A_TILE_H (128 * STRH)                 // 9216 halves
#define B_TILE_H (128 * STRH)                 // 9216 halves
#define STAGE_B  ((A_TILE_H + B_TILE_H) * 2)  // 36864 bytes
#define GSTAGES  3
#define GEMM_SMEM (GSTAGES * STAGE_B)         // 110592

__device__ __forceinline__ void gemm_load_stage(
    const __half* __restrict__ A, const __half* __restrict__ BT, int K,
    uint32_t sa, uint32_t sb, int brow, int bcol, int k0, int tid)
{
    #pragma unroll
    for (int i = 0; i < 8; i++) {           // A: 128 rows x 8 chunks, 128 thr
        int idx = tid + i * 128;            // 0..1023
        int row = idx >> 3;
        int c = idx & 7;
        cp_async16(sa + (row * STRH + c * 8) * 2,
                   &A[(size_t)(brow + row) * K + k0 + c * 8]);
    }
    #pragma unroll
    for (int i = 0; i < 8; i++) {           // B^T: 128 n-rows x 8 chunks
        int idx = tid + i * 128;
        int row = idx >> 3;
        int c = idx & 7;
        cp_async16(sb + (row * STRH + c * 8) * 2,
                   &BT[(size_t)(bcol + row) * K + k0 + c * 8]);
    }
}

// load one k16 fragment set (8 ldmatrix.x4: 4 A blocks + 4 B blocks)
#define LOAD_FRAGS(FA, FB, sa, sb, ko)                                        \
    do {                                                                      \
        ldm_x4((FA)[0],  (FA)[1],  (FA)[2],  (FA)[3],                         \
               (sa) + (la_off + (ko)) * 2);                                   \
        ldm_x4((FA)[4],  (FA)[5],  (FA)[6],  (FA)[7],                         \
               (sa) + (la_off + 16 * STRH + (ko)) * 2);                       \
        ldm_x4((FA)[8],  (FA)[9],  (FA)[10], (FA)[11],                        \
               (sa) + (la_off + 32 * STRH + (ko)) * 2);                       \
        ldm_x4((FA)[12], (FA)[13], (FA)[14], (FA)[15],                        \
               (sa) + (la_off + 48 * STRH + (ko)) * 2);                       \
        ldm_x4((FB)[0],  (FB)[1],  (FB)[2],  (FB)[3],                         \
               (sb) + (lb_off + (ko)) * 2);                                   \
        ldm_x4((FB)[4],  (FB)[5],  (FB)[6],  (FB)[7],                         \
               (sb) + (lb_off + 16 * STRH + (ko)) * 2);                       \
        ldm_x4((FB)[8],  (FB)[9],  (FB)[10], (FB)[11],                        \
               (sb) + (lb_off + 32 * STRH + (ko)) * 2);                       \
        ldm_x4((FB)[12], (FB)[13], (FB)[14], (FB)[15],                        \
               (sb) + (lb_off + 48 * STRH + (ko)) * 2);                       \
    } while (0)

#define MMA_BLOCK(cur)                                                        \
    do {                                                                      \
        _Pragma("unroll")                                                     \
        for (int j = 0; j < 4; j++) {                                         \
            _Pragma("unroll")                                                 \
            for (int i = 0; i < 4; i++) {                                     \
                mma_f16(acc[i][2 * j],                                        \
                        fa[cur][4 * i], fa[cur][4 * i + 1],                   \
                        fa[cur][4 * i + 2], fa[cur][4 * i + 3],               \
                        fb[cur][4 * j], fb[cur][4 * j + 1]);                  \
                mma_f16(acc[i][2 * j + 1],                                    \
                        fa[cur][4 * i], fa[cur][4 * i + 1],                   \
                        fa[cur][4 * i + 2], fa[cur][4 * i + 3],               \
                        fb[cur][4 * j + 2], fb[cur][4 * j + 3]);              \
            }                                                                 \
        }                                                                     \
    } while (0)

template <bool OUT_HALF, bool SCALE_Q>
__global__ __launch_bounds__(128, 2) void mma_gemm_bias(
    const __half* __restrict__ A, const __half* __restrict__ BT,
    const float* __restrict__ bias, void* __restrict__ Cv,
    int M, int N, int K)
{
    extern __shared__ char sm[];
    const int tid  = threadIdx.x;
    const int wid  = tid >> 5;
    const int lane = tid & 31;
    const int brow = blockIdx.y * GBM;
    const int bcol = blockIdx.x * GBN;
    const int warp_m = wid & 1;            // rows warp_m*64
    const int warp_n = wid >> 1;           // cols warp_n*64
    const int qr = lane >> 2;
    const int qc = lane & 3;

    const uint32_t base = smem_u32(sm);

    float acc[4][8][4];
    #pragma unroll
    for (int mt = 0; mt < 4; mt++)
        #pragma unroll
        for (int nt = 0; nt < 8; nt++)
            #pragma unroll
            for (int i = 0; i < 4; i++)
                acc[mt][nt][i] = 0.0f;

    const int KT = K / GBK;   // 32

    // Prologue: load stages for kt=0, kt=1 (depth 2, 3 physical stages)
    gemm_load_stage(A, BT, K, base, base + A_TILE_H * 2, brow, bcol, 0, tid);
    cp_commit();
    gemm_load_stage(A, BT, K, base + STAGE_B, base + STAGE_B + A_TILE_H * 2,
                    brow, bcol, GBK, tid);
    cp_commit();

    const int la_off = (warp_m * 64 + (lane & 15)) * STRH + (lane >> 4) * 8;
    const int g = lane >> 3;
    const int lb_off = (warp_n * 64 + ((g & 2) ? 8 : 0) + (lane & 7)) * STRH
                     + (g & 1) * 8;

    uint32_t fa[2][16], fb[2][16];

    cp_wait<1>();          // stage 0 resident (this thread)
    __syncthreads();       // ...and all threads' copies visible
    LOAD_FRAGS(fa[0], fb[0], base, base + A_TILE_H * 2, 0);

    int st = 0;
    for (int kt = 0; kt < KT; kt++) {
        // issue global loads for kt+2 into stage (kt+2)%3
        // (== stage kt-1, whose readers were proven done by last barrier)
        const int lkt = kt + 2;
        if (lkt < KT) {
            int fst = st + 2; if (fst >= GSTAGES) fst -= GSTAGES;
            const uint32_t pa = base + fst * STAGE_B;
            gemm_load_stage(A, BT, K, pa, pa + A_TILE_H * 2, brow, bcol,
                            lkt * GBK, tid);
        }
        cp_commit();

        const uint32_t sa = base + st * STAGE_B;
        const uint32_t sb = sa + A_TILE_H * 2;

        // k16 = 0..2: prefetch next k16 fragments (same stage), then MMA.
        #pragma unroll
        for (int k16 = 0; k16 < 3; k16++) {
            const int cur = k16 & 1, nxt = cur ^ 1;
            LOAD_FRAGS(fa[nxt], fb[nxt], sa, sb, (k16 + 1) * 16);
            MMA_BLOCK(cur);
        }

        // Rotated stage boundary: wait + barrier BEFORE the last MMA block;
        // next stage's k0 LDSM chain hides under MMA k3.
        cp_wait<1>();
        __syncthreads();
        int nst = st + 1; if (nst >= GSTAGES) nst -= GSTAGES;
        if (kt + 1 < KT) {
            const uint32_t na = base + nst * STAGE_B;
            LOAD_FRAGS(fa[0], fb[0], na, na + A_TILE_H * 2, 0);
        }
        MMA_BLOCK(1);
        st = nst;
    }

    // Epilogue
    #pragma unroll
    for (int mt = 0; mt < 4; mt++) {
        const int row0 = brow + warp_m * 64 + mt * 16 + qr;
        #pragma unroll
        for (int nt = 0; nt < 8; nt++) {
            const int col = bcol + warp_n * 64 + nt * 8 + 2 * qc;
            const float2 bb = *(const float2*)&bias[col];
            float vx = acc[mt][nt][0] + bb.x;
            float vy = acc[mt][nt][1] + bb.y;
            float wx = acc[mt][nt][2] + bb.x;
            float wy = acc[mt][nt][3] + bb.y;
            if (SCALE_Q && col < D_) {   // Q block: scale for log2 softmax
                vx *= QSCALE; vy *= QSCALE;
                wx *= QSCALE; wy *= QSCALE;
            }
            if (OUT_HALF) {
                __half* C = (__half*)Cv;
                *(uint32_t*)&C[(size_t)row0 * N + col]       = pack_h2(vx, vy);
                *(uint32_t*)&C[(size_t)(row0 + 8) * N + col] = pack_h2(wx, wy);
            } else {
                float* C = (float*)Cv;
                float2 o0; o0.x = vx; o0.y = vy;
                float2 o1; o1.x = wx; o1.y = wy;
                *(float2*)&C[(size_t)row0 * N + col]       = o0;
                *(float2*)&C[(size_t)(row0 + 8) * N + col] = o1;
            }
        }
    }
}

// ---------------------------------------------------------------------------
// fp16 tensor-core flash attention (causal, log2-domain register softmax).
// Q arrives pre-scaled by (1/sqrt(Dh))*log2e -> exp2(sub) only.
// CTA: 128 q-rows, 256 threads. KV tiles of 64, double-buffered cp.async.
// 2 CTAs/SM. Row stride 136 halves. S/PV fragments software-pipelined.
// ---------------------------------------------------------------------------
#define FBQ   128
#define FSTR  136
#define Q_BYTES     (128 * FSTR * 2)          // 34816
#define KV_TILE_B   (64 * FSTR * 2)           // 17408
#define KV_STAGE_B  (2 * KV_TILE_B)           // 34816
#define FLASH_SMEM  (Q_BYTES + 2 * KV_STAGE_B)  // 104448

__device__ __forceinline__ void load_kv_tile(
    uint32_t kbase, uint32_t vbase, size_t rowbase, int j0, int qcol, int tid)
{
    #pragma unroll
    for (int i = 0; i < 4; i++) {
        int idx = tid + i * 256;
        int r = idx >> 4;
        int c = idx & 15;
        cp_async16(kbase + (r * FSTR + c * 8) * 2,
                   &g_qkv[(rowbase + j0 + r) * (size_t)QKV_N + qcol + D_ + c * 8]);
    }
    #pragma unroll
    for (int i = 0; i < 4; i++) {
        int idx = tid + i * 256;
        int r = idx >> 4;
        int c = idx & 15;
        cp_async16(vbase + (r * FSTR + c * 8) * 2,
                   &g_qkv[(rowbase + j0 + r) * (size_t)QKV_N + qcol + 2 * D_ + c * 8]);
    }
}

__global__ __launch_bounds__(256, 2) void flash_mma_kernel()
{
    extern __shared__ char smc[];
    const int qi  = (gridDim.x - 1) - blockIdx.x;   // big q-blocks first
    const int q0  = qi * FBQ;
    const int h   = blockIdx.y;
    const int b   = blockIdx.z;
    const int tid = threadIdx.x;
    const int lane = tid & 31;
    const int wid  = tid >> 5;
    const int qr = lane >> 2;
    const int qc = lane & 3;

    const size_t rowbase = (size_t)b * T_;
    const int qcol = h * DH;

    const uint32_t base = smem_u32(smc);
    const uint32_t Qs = base;
    const int ntile = 2 * qi + 2;

    #pragma unroll
    for (int i = 0; i < 8; i++) {
        int idx = tid + i * 256;
        int r = idx >> 4;
        int c = idx & 15;
        cp_async16(Qs + (r * FSTR + c * 8) * 2,
                   &g_qkv[(rowbase + q0 + r) * (size_t)QKV_N + qcol + c * 8]);
    }
    {
        uint32_t s0 = base + Q_BYTES;
        load_kv_tile(s0, s0 + KV_TILE_B, rowbase, 0, qcol, tid);
        cp_commit();
        if (ntile > 1) {
            uint32_t s1 = base + Q_BYTES + KV_STAGE_B;
            load_kv_tile(s1, s1 + KV_TILE_B, rowbase, 64, qcol, tid);
        }
        cp_commit();
    }

    float oacc[16][4];
    #pragma unroll
    for (int n = 0; n < 16; n++)
        #pragma unroll
        for (int i = 0; i < 4; i++) oacc[n][i] = 0.0f;
    float mrow0 = -3.0e38f, mrow1 = -3.0e38f;
    float lrow0 = 0.0f, lrow1 = 0.0f;

    const int mloc = wid * 16;
    const int g = lane >> 3;
    const int lq_off = (mloc + (lane & 15)) * FSTR + (lane >> 4) * 8;
    const int lk_off = (((g & 2) ? 8 : 0) + (lane & 7)) * FSTR + (g & 1) * 8;
    const int lv_off = ((g & 1) * 8 + (lane & 7)) * FSTR + ((g & 2) ? 8 : 0);

    for (int t = 0; t < ntile; t++) {
        cp_wait<1>();
        __syncthreads();

        const uint32_t Ks = base + Q_BYTES + (t & 1) * KV_STAGE_B;
        const uint32_t Vs = Ks + KV_TILE_B;

        // ---- S = Q @ K^T (software-pipelined fragments) ----
        float sacc[8][4];
        #pragma unroll
        for (int n = 0; n < 8; n++)
            #pragma unroll
            for (int i = 0; i < 4; i++) sacc[n][i] = 0.0f;

        uint32_t qf[2][4], kf[2][4];
        ldm_x4(qf[0][0], qf[0][1], qf[0][2], qf[0][3], Qs + lq_off * 2);
        ldm_x4(kf[0][0], kf[0][1], kf[0][2], kf[0][3], Ks + lk_off * 2);
        #pragma unroll
        for (int k16 = 0; k16 < 8; k16++) {
            const int qb = k16 & 1;
            #pragma unroll
            for (int ntp = 0; ntp < 4; ntp++) {
                const int s = k16 * 4 + ntp;
                const int cur = s & 1, nxt = cur ^ 1;
                if (s < 31) {
                    const int sn = s + 1;
                    const int k16n = sn >> 2, ntpn = sn & 3;
                    ldm_x4(kf[nxt][0], kf[nxt][1], kf[nxt][2], kf[nxt][3],
                           Ks + (lk_off + ntpn * 16 * FSTR + k16n * 16) * 2);
                }
                if (ntp == 0 && k16 < 7) {
                    ldm_x4(qf[qb ^ 1][0], qf[qb ^ 1][1], qf[qb ^ 1][2],
                           qf[qb ^ 1][3], Qs + (lq_off + (k16 + 1) * 16) * 2);
                }
                mma_f16(sacc[2 * ntp    ], qf[qb][0], qf[qb][1], qf[qb][2],
                        qf[qb][3], kf[cur][0], kf[cur][1]);
                mma_f16(sacc[2 * ntp + 1], qf[qb][0], qf[qb][1], qf[qb][2],
                        qf[qb][3], kf[cur][2], kf[cur][3]);
            }
        }

        // ---- causal mask (only last 2 tiles touch the diagonal) ----
        if (t >= ntile - 2) {
            const int j0 = t * 64;
            const int rg0 = q0 + mloc + qr;
            const int rg1 = rg0 + 8;
            #pragma unroll
            for (int nt = 0; nt < 8; nt++) {
                const int cg = j0 + nt * 8 + 2 * qc;
                if (cg     > rg0) sacc[nt][0] = -1.0e30f;
                if (cg + 1 > rg0) sacc[nt][1] = -1.0e30f;
                if (cg     > rg1) sacc[nt][2] = -1.0e30f;
                if (cg + 1 > rg1) sacc[nt][3] = -1.0e30f;
            }
        }

        // ---- online softmax (log2 domain; exp2 of plain subtract) ----
        float mx0 = -3.0e38f, mx1 = -3.0e38f;
        #pragma unroll
        for (int nt = 0; nt < 8; nt++) {
            mx0 = fmaxf(mx0, fmaxf(sacc[nt][0], sacc[nt][1]));
            mx1 = fmaxf(mx1, fmaxf(sacc[nt][2], sacc[nt][3]));
        }
        mx0 = fmaxf(mx0, __shfl_xor_sync(0xFFFFFFFFu, mx0, 1));
        mx0 = fmaxf(mx0, __shfl_xor_sync(0xFFFFFFFFu, mx0, 2));
        mx1 = fmaxf(mx1, __shfl_xor_sync(0xFFFFFFFFu, mx1, 1));
        mx1 = fmaxf(mx1, __shfl_xor_sync(0xFFFFFFFFu, mx1, 2));
        const float mn0 = fmaxf(mrow0, mx0);
        const float mn1 = fmaxf(mrow1, mx1);
        const float al0 = fexp2(mrow0 - mn0);
        const float al1 = fexp2(mrow1 - mn1);
        mrow0 = mn0; mrow1 = mn1;

        // fused exp -> P-pack
        uint32_t pA[4][4];
        float ps0 = 0.0f, ps1 = 0.0f;
        #pragma unroll
        for (int j = 0; j < 4; j++) {
            float e00 = fexp2(sacc[2 * j][0] - mn0);
            float e01 = fexp2(sacc[2 * j][1] - mn0);
            float e02 = fexp2(sacc[2 * j][2] - mn1);
            float e03 = fexp2(sacc[2 * j][3] - mn1);
            float e10 = fexp2(sacc[2 * j + 1][0] - mn0);
            float e11 = fexp2(sacc[2 * j + 1][1] - mn0);
            float e12 = fexp2(sacc[2 * j + 1][2] - mn1);
            float e13 = fexp2(sacc[2 * j + 1][3] - mn1);
            ps0 += (e00 + e01) + (e10 + e11);
            ps1 += (e02 + e03) + (e12 + e13);
            pA[j][0] = pack_h2(e00, e01);
            pA[j][1] = pack_h2(e02, e03);
            pA[j][2] = pack_h2(e10, e11);
            pA[j][3] = pack_h2(e12, e13);
        }
        ps0 += __shfl_xor_sync(0xFFFFFFFFu, ps0, 1);
        ps0 += __shfl_xor_sync(0xFFFFFFFFu, ps0, 2);
        ps1 += __shfl_xor_sync(0xFFFFFFFFu, ps1, 1);
        ps1 += __shfl_xor_sync(0xFFFFFFFFu, ps1, 2);
        lrow0 = lrow0 * al0 + ps0;
        lrow1 = lrow1 * al1 + ps1;

        #pragma unroll
        for (int n = 0; n < 16; n++) {
            oacc[n][0] *= al0; oacc[n][1] *= al0;
            oacc[n][2] *= al1; oacc[n][3] *= al1;
        }

        // ---- O += P @ V (software-pipelined V fragments) ----
        uint32_t vf[2][4];
        ldm_x4_t(vf[0][0], vf[0][1], vf[0][2], vf[0][3], Vs + lv_off * 2);
        #pragma unroll
        for (int j = 0; j < 4; j++) {
            #pragma unroll
            for (int ntp = 0; ntp < 8; ntp++) {
                const int s = j * 8 + ntp;
                const int cur = s & 1, nxt = cur ^ 1;
                if (s < 31) {
                    const int sn = s + 1;
                    const int jn = sn >> 3, ntpn = sn & 7;
                    ldm_x4_t(vf[nxt][0], vf[nxt][1], vf[nxt][2], vf[nxt][3],
                             Vs + (lv_off + jn * 16 * FSTR + ntpn * 16) * 2);
                }
                mma_f16(oacc[2 * ntp    ], pA[j][0], pA[j][1], pA[j][2],
                        pA[j][3], vf[cur][0], vf[cur][1]);
                mma_f16(oacc[2 * ntp + 1], pA[j][0], pA[j][1], pA[j][2],
                        pA[j][3], vf[cur][2], vf[cur][3]);
            }
        }

        __syncthreads();
        if (t + 2 < ntile) {
            uint32_t sb = base + Q_BYTES + (t & 1) * KV_STAGE_B;
            load_kv_tile(sb, sb + KV_TILE_B, rowbase, (t + 2) * 64, qcol, tid);
        }
        cp_commit();
    }

    // ---- epilogue: normalize, fp16 store (feeds out-proj GEMM) ----
    const float li0 = 1.0f / lrow0;
    const float li1 = 1.0f / lrow1;
    const int r0 = q0 + mloc + qr;
    const int r1 = r0 + 8;
    #pragma unroll
    for (int ntd = 0; ntd < 16; ntd++) {
        const int col = qcol + ntd * 8 + 2 * qc;
        *(uint32_t*)&g_o[(rowbase + r0) * (size_t)D_ + col] =
            pack_h2(oacc[ntd][0] * li0, oacc[ntd][1] * li0);
        *(uint32_t*)&g_o[(rowbase + r1) * (size_t)D_ + col] =
            pack_h2(oacc[ntd][2] * li1, oacc[ntd][3] * li1);
    }
}

// ---------------------------------------------------------------------------
// Launch
// ---------------------------------------------------------------------------
extern "C" void kernel_launch(void* const* d_in, const int* in_sizes, int n_in,
                              void* d_out, int out_size)
{
    (void)in_sizes; (void)n_in; (void)out_size;
    const float* x    = (const float*)d_in[0];
    const float* Wqkv = (const float*)d_in[1];
    const float* bqkv = (const float*)d_in[2];
    const float* Wout = (const float*)d_in[3];
    const float* bout = (const float*)d_in[4];
    float* out = (float*)d_out;

    static __half *qkv_ptr = nullptr, *o_ptr = nullptr, *xh_ptr = nullptr;
    static __half *wqkvT_ptr = nullptr, *woutT_ptr = nullptr;
    static bool init_done = false;
    if (!init_done) {
        // First call is the (uncaptured) correctness run; these immediate host
        // APIs never land inside graph capture.
        cudaFuncSetAttribute(flash_mma_kernel,
                             cudaFuncAttributeMaxDynamicSharedMemorySize,
                             FLASH_SMEM);
        cudaFuncSetAttribute(mma_gemm_bias<true, true>,
                             cudaFuncAttributeMaxDynamicSharedMemorySize,
                             GEMM_SMEM);
        cudaFuncSetAttribute(mma_gemm_bias<false, false>,
                             cudaFuncAttributeMaxDynamicSharedMemorySize,
                             GEMM_SMEM);
        void* p;
        cudaGetSymbolAddress(&p, g_qkv);   qkv_ptr   = (__half*)p;
        cudaGetSymbolAddress(&p, g_o);     o_ptr     = (__half*)p;
        cudaGetSymbolAddress(&p, g_xh);    xh_ptr    = (__half*)p;
        cudaGetSymbolAddress(&p, g_WqkvT); wqkvT_ptr = (__half*)p;
        cudaGetSymbolAddress(&p, g_WoutT); woutT_ptr = (__half*)p;
        init_done = true;
    }

    // 0) pre-pass: x -> fp16; weights -> transposed fp16 [N,K]
    f2h_kernel<<<(MROWS * (size_t)D_ / 8) / 256, 256>>>(x, xh_ptr);
    transpose_kernel<<<dim3(QKV_N / 64, D_ / 64), 256>>>(Wqkv, wqkvT_ptr, D_, QKV_N);
    transpose_kernel<<<dim3(D_ / 64, D_ / 64), 256>>>(Wout, woutT_ptr, D_, D_);

    // 1) QKV = x @ Wqkv + bqkv (fp16 mma; Q pre-scaled by s*log2e)
    mma_gemm_bias<true, true><<<dim3(QKV_N / GBN, MROWS / GBM), 128, GEMM_SMEM>>>(
        xh_ptr, wqkvT_ptr, bqkv, qkv_ptr, MROWS, QKV_N, D_);

    // 2) causal flash attention (fp16 tensor cores) -> g_o (fp16)
    flash_mma_kernel<<<dim3(T_ / FBQ, H_, B_), 256, FLASH_SMEM>>>();

    // 3) out = g_o @ Wout + bout (fp16 mma, fp32 output)
    mma_gemm_bias<false, false><<<dim3(D_ / GBN, MROWS / GBM), 128, GEMM_SMEM>>>(
        o_ptr, woutT_ptr, bout, out, MROWS, D_, D_);
}